// round 13
// baseline (speedup 1.0000x reference)
#include <cuda_runtime.h>
#include <cstdint>

// Problem constants
#define NB      8192
#define ND      256
#define MAXPOS  1536
#define INV_T   14.285714285714286f
#define LOG2E   1.4426950408889634f
#define PSCALE  (INV_T / 16129.0f)            // int-acc -> s/T
#define EXCI    (INV_T * LOG2E / 16129.0f)    // int-acc -> log2(exp(s/T))
#define EPSL    1e-8f
#define ROWSTR  272                   // smem row stride (256 int8 + 16B pad)
#define NTILE_D 64
#define NTILES  2080                  // 64*65/2 upper-tri tiles
#define GRIDM   296                   // 2 CTAs/SM x 148 SMs (all resident)

// ---- scratch (__device__ globals; no allocation) ----
__device__ float    g_negsum[NB];
__device__ int      g_poscnt[NB];
__device__ float    g_pos[(size_t)NB * MAXPOS];   // 48 MB
__device__ float    g_total;
__device__ int      g_nvalid;
__device__ int      g_lab[NB];
__device__ int      g_bar1, g_bar2;
__device__ uint8_t  g_i8[(size_t)NB * ND];        // 2 MB int8 features

// ============================ helpers ============================
__device__ __forceinline__ uint32_t smem_u32(const void* p) {
    uint32_t a;
    asm("{ .reg .u64 t; cvta.to.shared.u64 t, %1; cvt.u32.u64 %0, t; }" : "=r"(a) : "l"(p));
    return a;
}
__device__ __forceinline__ void ldsm_x4(uint32_t* r, uint32_t addr) {
    asm volatile("ldmatrix.sync.aligned.m8n8.x4.shared.b16 {%0,%1,%2,%3}, [%4];"
                 : "=r"(r[0]), "=r"(r[1]), "=r"(r[2]), "=r"(r[3]) : "r"(addr));
}
__device__ __forceinline__ void mma_s8(int* c, const uint32_t* a,
                                       uint32_t b0, uint32_t b1) {
    asm volatile(
        "mma.sync.aligned.m16n8k32.row.col.s32.s8.s8.s32 "
        "{%0,%1,%2,%3}, {%4,%5,%6,%7}, {%8,%9}, {%0,%1,%2,%3};"
        : "+r"(c[0]), "+r"(c[1]), "+r"(c[2]), "+r"(c[3])
        : "r"(a[0]), "r"(a[1]), "r"(a[2]), "r"(a[3]), "r"(b0), "r"(b1));
}
__device__ __forceinline__ void cp16(uint32_t dst, const void* src) {
    asm volatile("cp.async.cg.shared.global [%0], [%1], 16;" :: "r"(dst), "l"(src));
}
#define CP_COMMIT() asm volatile("cp.async.commit_group;" ::: "memory")
#define CP_WAIT0()  asm volatile("cp.async.wait_group 0;" ::: "memory")
__device__ __forceinline__ float ex2(float x) {
    float y; asm("ex2.approx.ftz.f32 %0, %1;" : "=f"(y) : "f"(x)); return y;
}

// ============================ k_conv: int8 quantize + init ============================
__global__ void k_conv(const float* __restrict__ f, const void* __restrict__ labels) {
    __shared__ int s_is64;
    const int gid = blockIdx.x * blockDim.x + threadIdx.x;

    float4 v = ((const float4*)f)[gid];
    int r0 = __float2int_rn(v.x * 127.0f);
    int r1 = __float2int_rn(v.y * 127.0f);
    int r2 = __float2int_rn(v.z * 127.0f);
    int r3 = __float2int_rn(v.w * 127.0f);
    ((uint32_t*)g_i8)[gid] = (uint32_t)(r0 & 255) | ((uint32_t)(r1 & 255) << 8)
                           | ((uint32_t)(r2 & 255) << 16) | ((uint32_t)(r3 & 255) << 24);

    if (gid < NB) { g_negsum[gid] = 0.0f; g_poscnt[gid] = 0; }
    if (gid == 0) { g_total = 0.0f; g_nvalid = 0; g_bar1 = 0; g_bar2 = 0; }

    if (blockIdx.x == 0) {
        if (threadIdx.x == 0) {
            const int* l32 = (const int*)labels;
            int all0 = 1;
            #pragma unroll 1
            for (int t = 1; t < 128; t += 2)
                if (l32[t] != 0) { all0 = 0; break; }
            s_is64 = all0;
        }
        __syncthreads();
        const int is64 = s_is64;
        for (int i = threadIdx.x; i < NB; i += 256)
            g_lab[i] = is64 ? (int)((const long long*)labels)[i]
                            : ((const int*)labels)[i];
    }
}

// ============================ fused persistent kernel ============================
#define SM_A   0
#define SM_B0  (128 * ROWSTR)
#define SM_B1  (2 * 128 * ROWSTR)
#define SM_TOT (3 * 128 * ROWSTR)     // 104,448 B -> 2 CTAs/SM

extern __shared__ char dsm[];

__global__ void __launch_bounds__(256, 2) k_fused(float* __restrict__ out) {
    const int tid  = threadIdx.x;
    const int warp = tid >> 5;
    const int lane = tid & 31;
    const int warpRow = warp & 3;
    const int warpCol = warp >> 2;

    // ---------------- Phase 1: triangular tiled GEMM + classify ----------------
    const int start = (int)(((long long)blockIdx.x * NTILES) / GRIDM);
    const int end   = (int)(((long long)(blockIdx.x + 1) * NTILES) / GRIDM);

    const uint32_t smb = smem_u32(dsm);

    const uint32_t aBase = smb + SM_A
        + (uint32_t)(warpRow * 32 + ((lane >> 3) & 1) * 8 + (lane & 7)) * ROWSTR
        + (lane >> 4) * 16;
    const uint32_t bRowOff =
        (uint32_t)(warpCol * 64 + (lane >> 4) * 8 + (lane & 7)) * ROWSTR
        + ((lane >> 3) & 1) * 16;

    int rloc[4];
    #pragma unroll
    for (int idx = 0; idx < 4; idx++)
        rloc[idx] = warpRow * 32 + (idx >> 1) * 16 + (idx & 1) * 8 + (lane >> 2);

    if (start < end) {
        int I = 0, base = 0;
        while (base + (NTILE_D - I) <= start) { base += NTILE_D - I; I++; }
        int J = I + (start - base);

        {   // prologue loads
            const uint4* srcA = (const uint4*)(g_i8 + (size_t)I * 128 * ND);
            const uint4* srcB = (const uint4*)(g_i8 + (size_t)J * 128 * ND);
            #pragma unroll
            for (int i = 0; i < 8; i++) {
                int u = tid + i * 256;
                int row = u >> 4, q = u & 15;
                cp16(smb + SM_A  + row * ROWSTR + q * 16, srcA + u);
                cp16(smb + SM_B0 + row * ROWSTR + q * 16, srcB + u);
            }
            CP_COMMIT();
        }

        for (int t = start; t < end; t++) {
            const int buf = (t - start) & 1;
            int nI = I, nJ = J + 1;
            if (nJ == NTILE_D) { nI = I + 1; nJ = nI; }
            const bool haveNext = (t + 1 < end);

            CP_WAIT0();
            __syncthreads();

            // ---- int8 GEMM: 128x128 tile, K=256, warp tile 32x64 ----
            int acc[2][8][4];
            #pragma unroll
            for (int mt = 0; mt < 2; mt++)
                #pragma unroll
                for (int nt = 0; nt < 8; nt++)
                    #pragma unroll
                    for (int c = 0; c < 4; c++) acc[mt][nt][c] = 0;

            const uint32_t bBase = (buf ? smb + SM_B1 : smb + SM_B0) + bRowOff;
            #pragma unroll
            for (int ks = 0; ks < 8; ks++) {
                const uint32_t koff = ks * 32;
                uint32_t a[2][4], b[4][4];
                ldsm_x4(a[0], aBase + koff);
                ldsm_x4(a[1], aBase + 16 * ROWSTR + koff);
                #pragma unroll
                for (int nt2 = 0; nt2 < 4; nt2++)
                    ldsm_x4(b[nt2], bBase + nt2 * 16 * ROWSTR + koff);
                #pragma unroll
                for (int mt = 0; mt < 2; mt++)
                    #pragma unroll
                    for (int nt = 0; nt < 8; nt++)
                        mma_s8(acc[mt][nt], a[mt],
                               b[nt >> 1][(nt & 1) * 2], b[nt >> 1][(nt & 1) * 2 + 1]);
            }

            __syncthreads();   // all warps done reading A, B[buf]

            // prefetch next tile under epilogue
            if (haveNext) {
                const uint4* srcB = (const uint4*)(g_i8 + (size_t)nJ * 128 * ND);
                const uint32_t dstB = buf ? (smb + SM_B0) : (smb + SM_B1);
                #pragma unroll
                for (int i = 0; i < 8; i++) {
                    int u = tid + i * 256;
                    int row = u >> 4, q = u & 15;
                    cp16(dstB + row * ROWSTR + q * 16, srcB + u);
                }
                if (nI != I) {
                    const uint4* srcA = (const uint4*)(g_i8 + (size_t)nI * 128 * ND);
                    #pragma unroll
                    for (int i = 0; i < 8; i++) {
                        int u = tid + i * 256;
                        int row = u >> 4, q = u & 15;
                        cp16(smb + SM_A + row * ROWSTR + q * 16, srcA + u);
                    }
                }
                CP_COMMIT();
            }

            // ---- epilogue: double-accounted classify/scatter ----
            const int rowBase = I * 128;
            const int colBase = J * 128;
            const bool diag   = (I == J);

            int lblC16[16];
            #pragma unroll
            for (int c2 = 0; c2 < 16; c2++) {
                const int col = warpCol * 64 + (c2 >> 1) * 8 + 2 * (lane & 3) + (c2 & 1);
                lblC16[c2] = g_lab[colBase + col];
            }

            #pragma unroll
            for (int idx = 0; idx < 4; idx++) {
                const int mt = idx >> 1, h = idx & 1;
                const int r    = rloc[idx];
                const int grow = rowBase + r;
                const int lr   = g_lab[grow];

                uint32_t pmask = 0;
                #pragma unroll
                for (int c2 = 0; c2 < 16; c2++) {
                    const int col = warpCol * 64 + (c2 >> 1) * 8 + 2 * (lane & 3) + (c2 & 1);
                    const bool skip = diag && (col <= r);
                    if (!skip && lblC16[c2] == lr) pmask |= 1u << c2;
                }
                if (pmask) {
                    int w = atomicAdd(&g_poscnt[grow], __popc(pmask));
                    float* dstR = &g_pos[(size_t)grow * MAXPOS];
                    uint32_t m = pmask;
                    while (m) {
                        const int b = __ffs(m) - 1; m &= m - 1;
                        const float val = (float)acc[mt][b >> 1][h * 2 + (b & 1)] * PSCALE;
                        if (w < MAXPOS) dstR[w] = val;
                        w++;
                        const int col  = warpCol * 64 + (b >> 1) * 8 + 2 * (lane & 3) + (b & 1);
                        const int gcol = colBase + col;
                        int wc = atomicAdd(&g_poscnt[gcol], 1);
                        if (wc < MAXPOS) g_pos[(size_t)gcol * MAXPOS + wc] = val;
                    }
                }
                // overwrite acc with bit-cast exp (negatives) or 0
                float rs = 0.0f;
                #pragma unroll
                for (int c2 = 0; c2 < 16; c2++) {
                    const int col = warpCol * 64 + (c2 >> 1) * 8 + 2 * (lane & 3) + (c2 & 1);
                    const bool skip = (diag && (col <= r)) || ((pmask >> c2) & 1);
                    int* ap = &acc[mt][c2 >> 1][h * 2 + (c2 & 1)];
                    const float e = skip ? 0.0f : ex2((float)(*ap) * EXCI);
                    *ap = __float_as_int(e);
                    rs += e;
                }
                rs += __shfl_xor_sync(0xffffffffu, rs, 1);
                rs += __shfl_xor_sync(0xffffffffu, rs, 2);
                if ((lane & 3) == 0 && rs != 0.0f) atomicAdd(&g_negsum[grow], rs);
            }

            // column-side neg sums
            #pragma unroll
            for (int c2 = 0; c2 < 16; c2++) {
                float cs = __int_as_float(acc[0][c2 >> 1][(c2 & 1)])
                         + __int_as_float(acc[0][c2 >> 1][2 + (c2 & 1)])
                         + __int_as_float(acc[1][c2 >> 1][(c2 & 1)])
                         + __int_as_float(acc[1][c2 >> 1][2 + (c2 & 1)]);
                cs += __shfl_xor_sync(0xffffffffu, cs, 4);
                cs += __shfl_xor_sync(0xffffffffu, cs, 8);
                cs += __shfl_xor_sync(0xffffffffu, cs, 16);
                if (lane < 4 && cs != 0.0f) {
                    const int col = warpCol * 64 + (c2 >> 1) * 8 + 2 * lane + (c2 & 1);
                    atomicAdd(&g_negsum[colBase + col], cs);
                }
            }

            I = nI; J = nJ;
        }
    }

    // ---------------- device-wide barrier (all 296 CTAs resident) ----------------
    __syncthreads();
    __threadfence();
    if (tid == 0) {
        atomicAdd(&g_bar1, 1);
        while (*(volatile int*)&g_bar1 < GRIDM) __nanosleep(64);
    }
    __syncthreads();
    __threadfence();

    // ---------------- Phase 2: per-row loss ----------------
    for (int row = blockIdx.x * 8 + warp; row < NB; row += GRIDM * 8) {
        const float neg = g_negsum[row];
        const int   np  = g_poscnt[row];
        const int   m   = np < MAXPOS ? np : MAXPOS;

        const float4* rowp = (const float4*)&g_pos[(size_t)row * MAXPOS];
        float s = 0.0f;
        for (int c = lane; c * 4 < m; c += 32) {
            float4 v = rowp[c];
            const int bb = c * 4;
            float vv[4] = {v.x, v.y, v.z, v.w};
            #pragma unroll
            for (int k = 0; k < 4; k++) {
                if (bb + k < m) {
                    float e = ex2(vv[k] * LOG2E);
                    // -log(e/(e+neg)+eps) == log(e+neg) - log(e + eps*(e+neg))
                    s += __logf(e + neg) - __logf(fmaf(EPSL, e + neg, e));
                }
            }
        }
        #pragma unroll
        for (int o = 16; o > 0; o >>= 1)
            s += __shfl_xor_sync(0xffffffffu, s, o);

        if (lane == 0 && np > 0) {     // num_neg = NB-1-np > 0 always
            atomicAdd(&g_total, s / (float)np);
            atomicAdd(&g_nvalid, 1);
        }
    }

    // ---------------- final: last CTA writes the scalar ----------------
    __syncthreads();
    __threadfence();
    if (tid == 0) {
        int d = atomicAdd(&g_bar2, 1);
        if (d == GRIDM - 1) {
            float tot = *(volatile float*)&g_total;
            int   nv  = *(volatile int*)&g_nvalid;
            out[0] = (nv > 0) ? tot / (float)nv : 0.0f;
        }
    }
}

// ---------------------------------------------------------------------------
extern "C" void kernel_launch(void* const* d_in, const int* in_sizes, int n_in,
                              void* d_out, int out_size) {
    const float* feats  = (const float*)d_in[0];
    const void*  labels = d_in[1];

    cudaFuncSetAttribute(k_fused, cudaFuncAttributeMaxDynamicSharedMemorySize, SM_TOT);

    k_conv<<<(NB * ND / 4) / 256, 256>>>(feats, labels);
    k_fused<<<GRIDM, 256, SM_TOT>>>((float*)d_out);
}

// round 14
// speedup vs baseline: 1.2266x; 1.2266x over previous
#include <cuda_runtime.h>
#include <cstdint>

// Problem constants
#define NB      8192
#define ND      256
#define MAXPOS  1536
#define INV_T   14.285714285714286f
#define EXC     20.617439059314203f   // INV_T * log2(e)
#define LOG2E   1.4426950408889634f
#define EPSL    1e-8f
#define ROWSTR  272                   // smem row stride (256 fp8 + 16B pad)
#define NTILE_D 64
#define NTILES  2080                  // 64*65/2 upper-tri tiles
#define GRIDM   296                   // 2 CTAs/SM x 148 SMs (all resident)

// ---- scratch (__device__ globals; zero-initialized, no allocation) ----
__device__ float    g_negsum[NB];
__device__ int      g_poscnt[NB];
__device__ float    g_pos[(size_t)NB * MAXPOS];   // 48 MB
__device__ float    g_total;
__device__ int      g_nvalid;
__device__ int      g_lab[NB];
__device__ int      g_bar0, g_bar1, g_bar2, g_ctr;
__device__ uint8_t  g_f8[(size_t)NB * ND];        // 2 MB e4m3 features

// ============================ helpers ============================
__device__ __forceinline__ uint32_t smem_u32(const void* p) {
    uint32_t a;
    asm("{ .reg .u64 t; cvta.to.shared.u64 t, %1; cvt.u32.u64 %0, t; }" : "=r"(a) : "l"(p));
    return a;
}
__device__ __forceinline__ void ldsm_x4(uint32_t* r, uint32_t addr) {
    asm volatile("ldmatrix.sync.aligned.m8n8.x4.shared.b16 {%0,%1,%2,%3}, [%4];"
                 : "=r"(r[0]), "=r"(r[1]), "=r"(r[2]), "=r"(r[3]) : "r"(addr));
}
__device__ __forceinline__ void mma_fp8(float* c, const uint32_t* a,
                                        uint32_t b0, uint32_t b1) {
    asm volatile(
        "mma.sync.aligned.m16n8k32.row.col.f32.e4m3.e4m3.f32 "
        "{%0,%1,%2,%3}, {%4,%5,%6,%7}, {%8,%9}, {%0,%1,%2,%3};"
        : "+f"(c[0]), "+f"(c[1]), "+f"(c[2]), "+f"(c[3])
        : "r"(a[0]), "r"(a[1]), "r"(a[2]), "r"(a[3]), "r"(b0), "r"(b1));
}
__device__ __forceinline__ void cp16(uint32_t dst, const void* src) {
    asm volatile("cp.async.cg.shared.global [%0], [%1], 16;" :: "r"(dst), "l"(src));
}
#define CP_COMMIT() asm volatile("cp.async.commit_group;" ::: "memory")
#define CP_WAIT0()  asm volatile("cp.async.wait_group 0;" ::: "memory")
__device__ __forceinline__ float ex2(float x) {
    float y; asm("ex2.approx.ftz.f32 %0, %1;" : "=f"(y) : "f"(x)); return y;
}
__device__ __forceinline__ uint16_t cvt8x2(float hi, float lo) {
    uint16_t h;
    asm("cvt.rn.satfinite.e4m3x2.f32 %0, %1, %2;" : "=h"(h) : "f"(hi), "f"(lo));
    return h;
}
__device__ __forceinline__ void gbar(int* ctr) {
    __syncthreads();
    __threadfence();
    if (threadIdx.x == 0) {
        atomicAdd(ctr, 1);
        while (*(volatile int*)ctr < GRIDM) __nanosleep(32);
    }
    __syncthreads();
    __threadfence();
}

// ============================ fused persistent kernel ============================
#define SM_A   0
#define SM_B   (128 * ROWSTR)
#define SM_TOT (2 * 128 * ROWSTR)     // 69,632 B -> 2 CTAs/SM

extern __shared__ char dsm[];

__global__ void __launch_bounds__(256, 2) k_all(float* __restrict__ out,
                                                const float* __restrict__ feats,
                                                const void*  __restrict__ labels) {
    __shared__ int s_t, s_I, s_J, s_is64;

    const int tid  = threadIdx.x;
    const int warp = tid >> 5;
    const int lane = tid & 31;
    const int warpRow = warp & 3;
    const int warpCol = warp >> 2;
    const uint32_t smb = smem_u32(dsm);

    // ---------------- Phase 0: convert + init ----------------
    for (int i = blockIdx.x * 256 + tid; i < NB * ND / 4; i += GRIDM * 256) {
        float4 v = ((const float4*)feats)[i];
        uint32_t lo = cvt8x2(v.y, v.x);
        uint32_t hi = cvt8x2(v.w, v.z);
        ((uint32_t*)g_f8)[i] = lo | (hi << 16);
    }
    for (int i = blockIdx.x * 256 + tid; i < NB; i += GRIDM * 256) {
        g_negsum[i] = 0.0f; g_poscnt[i] = 0;
    }
    if (blockIdx.x == 0 && tid == 0) { g_total = 0.0f; g_nvalid = 0; }
    if (blockIdx.x < 32) {            // labels: 32 CTAs x 256 each
        if (tid == 0) {
            const int* l32 = (const int*)labels;
            int all0 = 1;
            #pragma unroll 1
            for (int t = 1; t < 128; t += 2)
                if (l32[t] != 0) { all0 = 0; break; }
            s_is64 = all0;
        }
        __syncthreads();
        const int i = blockIdx.x * 256 + tid;
        g_lab[i] = s_is64 ? (int)((const long long*)labels)[i]
                          : ((const int*)labels)[i];
    }

    gbar(&g_bar0);                    // features + labels + zeros published

    // ---------------- Phase 1: dynamic triangular tiles ----------------
    const uint32_t aBase = smb + SM_A
        + (uint32_t)(warpRow * 32 + ((lane >> 3) & 1) * 8 + (lane & 7)) * ROWSTR
        + (lane >> 4) * 16;
    const uint32_t bBase = smb + SM_B
        + (uint32_t)(warpCol * 64 + (lane >> 4) * 8 + (lane & 7)) * ROWSTR
        + ((lane >> 3) & 1) * 16;

    int rloc[4];
    #pragma unroll
    for (int idx = 0; idx < 4; idx++)
        rloc[idx] = warpRow * 32 + (idx >> 1) * 16 + (idx & 1) * 8 + (lane >> 2);

    // initial grab + decode (tid 0)
    if (tid == 0) {
        int t0 = atomicAdd(&g_ctr, 1);
        s_t = t0;
        if (t0 < NTILES) {
            int Ii = (int)((129.0 - sqrt(16641.0 - 8.0 * (double)t0)) * 0.5);
            while (Ii > 0 && Ii * (129 - Ii) / 2 > t0) Ii--;
            while ((Ii + 1) * (128 - Ii) / 2 <= t0) Ii++;
            s_I = Ii; s_J = Ii + (t0 - Ii * (129 - Ii) / 2);
        }
    }
    __syncthreads();
    int tcur = s_t, I = s_I, J = s_J;

    if (tcur < NTILES) {
        const uint4* srcA = (const uint4*)(g_f8 + (size_t)I * 128 * ND);
        const uint4* srcB = (const uint4*)(g_f8 + (size_t)J * 128 * ND);
        #pragma unroll
        for (int i = 0; i < 8; i++) {
            int u = tid + i * 256;
            int row = u >> 4, q = u & 15;
            cp16(smb + SM_A + row * ROWSTR + q * 16, srcA + u);
            cp16(smb + SM_B + row * ROWSTR + q * 16, srcB + u);
        }
        CP_COMMIT();
    }

    while (tcur < NTILES) {
        // grab next tile (published at the pre-GEMM sync)
        if (tid == 0) {
            int tn = atomicAdd(&g_ctr, 1);
            s_t = tn;
            if (tn < NTILES) {
                int Ii = (int)((129.0 - sqrt(16641.0 - 8.0 * (double)tn)) * 0.5);
                while (Ii > 0 && Ii * (129 - Ii) / 2 > tn) Ii--;
                while ((Ii + 1) * (128 - Ii) / 2 <= tn) Ii++;
                s_I = Ii; s_J = Ii + (tn - Ii * (129 - Ii) / 2);
            }
        }
        CP_WAIT0();
        __syncthreads();              // A,B visible + s_t/s_I/s_J published
        const int tn = s_t, In = s_I, Jn = s_J;

        // ---- fp8 GEMM: 128x128 tile, K=256, warp tile 32x64 ----
        float acc[2][8][4];
        #pragma unroll
        for (int mt = 0; mt < 2; mt++)
            #pragma unroll
            for (int nt = 0; nt < 8; nt++)
                #pragma unroll
                for (int c = 0; c < 4; c++) acc[mt][nt][c] = 0.0f;

        #pragma unroll
        for (int ks = 0; ks < 8; ks++) {
            const uint32_t koff = ks * 32;
            uint32_t a[2][4], b[4][4];
            ldsm_x4(a[0], aBase + koff);
            ldsm_x4(a[1], aBase + 16 * ROWSTR + koff);
            #pragma unroll
            for (int nt2 = 0; nt2 < 4; nt2++)
                ldsm_x4(b[nt2], bBase + nt2 * 16 * ROWSTR + koff);
            #pragma unroll
            for (int mt = 0; mt < 2; mt++)
                #pragma unroll
                for (int nt = 0; nt < 8; nt++)
                    mma_fp8(acc[mt][nt], a[mt],
                            b[nt >> 1][(nt & 1) * 2], b[nt >> 1][(nt & 1) * 2 + 1]);
        }
        __syncthreads();              // all warps done reading A,B

        // prefetch next tile's A+B (hidden under epilogue)
        if (tn < NTILES) {
            const uint4* srcA = (const uint4*)(g_f8 + (size_t)In * 128 * ND);
            const uint4* srcB = (const uint4*)(g_f8 + (size_t)Jn * 128 * ND);
            #pragma unroll
            for (int i = 0; i < 8; i++) {
                int u = tid + i * 256;
                int row = u >> 4, q = u & 15;
                cp16(smb + SM_A + row * ROWSTR + q * 16, srcA + u);
                cp16(smb + SM_B + row * ROWSTR + q * 16, srcB + u);
            }
            CP_COMMIT();
        }

        // ---- epilogue: double-accounted classify/scatter ----
        const int rowBase = I * 128;
        const int colBase = J * 128;
        const bool diag   = (I == J);

        int lblC16[16];
        #pragma unroll
        for (int c2 = 0; c2 < 16; c2++) {
            const int col = warpCol * 64 + (c2 >> 1) * 8 + 2 * (lane & 3) + (c2 & 1);
            lblC16[c2] = g_lab[colBase + col];
        }

        #pragma unroll
        for (int idx = 0; idx < 4; idx++) {
            const int mt = idx >> 1, h = idx & 1;
            const int r    = rloc[idx];
            const int grow = rowBase + r;
            const int lr   = g_lab[grow];

            uint32_t pmask = 0;
            #pragma unroll
            for (int c2 = 0; c2 < 16; c2++) {
                const int col = warpCol * 64 + (c2 >> 1) * 8 + 2 * (lane & 3) + (c2 & 1);
                const bool skip = diag && (col <= r);
                if (!skip && lblC16[c2] == lr) pmask |= 1u << c2;
            }
            if (pmask) {
                int w = atomicAdd(&g_poscnt[grow], __popc(pmask));
                float* dstR = &g_pos[(size_t)grow * MAXPOS];
                uint32_t m = pmask;
                while (m) {
                    const int b = __ffs(m) - 1; m &= m - 1;
                    const float val = acc[mt][b >> 1][h * 2 + (b & 1)] * INV_T;
                    if (w < MAXPOS) dstR[w] = val;
                    w++;
                    const int col  = warpCol * 64 + (b >> 1) * 8 + 2 * (lane & 3) + (b & 1);
                    const int gcol = colBase + col;
                    int wc = atomicAdd(&g_poscnt[gcol], 1);
                    if (wc < MAXPOS) g_pos[(size_t)gcol * MAXPOS + wc] = val;
                }
            }
            float rs = 0.0f;
            #pragma unroll
            for (int c2 = 0; c2 < 16; c2++) {
                const int col = warpCol * 64 + (c2 >> 1) * 8 + 2 * (lane & 3) + (c2 & 1);
                const bool skip = (diag && (col <= r)) || ((pmask >> c2) & 1);
                float* ap = &acc[mt][c2 >> 1][h * 2 + (c2 & 1)];
                const float e = skip ? 0.0f : ex2(*ap * EXC);
                *ap = e;
                rs += e;
            }
            rs += __shfl_xor_sync(0xffffffffu, rs, 1);
            rs += __shfl_xor_sync(0xffffffffu, rs, 2);
            if ((lane & 3) == 0 && rs != 0.0f) atomicAdd(&g_negsum[grow], rs);
        }

        #pragma unroll
        for (int c2 = 0; c2 < 16; c2++) {
            float cs = acc[0][c2 >> 1][(c2 & 1)] + acc[0][c2 >> 1][2 + (c2 & 1)]
                     + acc[1][c2 >> 1][(c2 & 1)] + acc[1][c2 >> 1][2 + (c2 & 1)];
            cs += __shfl_xor_sync(0xffffffffu, cs, 4);
            cs += __shfl_xor_sync(0xffffffffu, cs, 8);
            cs += __shfl_xor_sync(0xffffffffu, cs, 16);
            if (lane < 4 && cs != 0.0f) {
                const int col = warpCol * 64 + (c2 >> 1) * 8 + 2 * lane + (c2 & 1);
                atomicAdd(&g_negsum[colBase + col], cs);
            }
        }

        tcur = tn; I = In; J = Jn;
    }

    gbar(&g_bar1);                    // all neg sums + positive lists final

    // ---------------- Phase 2: per-row loss (L2-hot) ----------------
    for (int row = blockIdx.x * 8 + warp; row < NB; row += GRIDM * 8) {
        const float neg = g_negsum[row];
        const int   np  = g_poscnt[row];
        const int   m   = np < MAXPOS ? np : MAXPOS;

        const float4* rowp = (const float4*)&g_pos[(size_t)row * MAXPOS];
        float s = 0.0f;
        for (int c = lane; c * 4 < m; c += 32) {
            float4 v = rowp[c];
            const int bb = c * 4;
            float vv[4] = {v.x, v.y, v.z, v.w};
            #pragma unroll
            for (int k = 0; k < 4; k++) {
                if (bb + k < m) {
                    float e = ex2(vv[k] * LOG2E);
                    // -log(e/(e+neg)+eps) == log(e+neg) - log(e + eps*(e+neg))
                    s += __logf(e + neg) - __logf(fmaf(EPSL, e + neg, e));
                }
            }
        }
        #pragma unroll
        for (int o = 16; o > 0; o >>= 1)
            s += __shfl_xor_sync(0xffffffffu, s, o);

        if (lane == 0 && np > 0) {    // num_neg = NB-1-np > 0 always
            atomicAdd(&g_total, s / (float)np);
            atomicAdd(&g_nvalid, 1);
        }
    }

    // ---------------- final: last CTA writes scalar + resets state ----------------
    __syncthreads();
    __threadfence();
    if (tid == 0) {
        int d = atomicAdd(&g_bar2, 1);
        if (d == GRIDM - 1) {
            float tot = *(volatile float*)&g_total;
            int   nv  = *(volatile int*)&g_nvalid;
            out[0] = (nv > 0) ? tot / (float)nv : 0.0f;
            g_bar0 = 0; g_bar1 = 0; g_bar2 = 0; g_ctr = 0;   // graph-replay reset
        }
    }
}

// ---------------------------------------------------------------------------
extern "C" void kernel_launch(void* const* d_in, const int* in_sizes, int n_in,
                              void* d_out, int out_size) {
    const float* feats  = (const float*)d_in[0];
    const void*  labels = d_in[1];

    cudaFuncSetAttribute(k_all, cudaFuncAttributeMaxDynamicSharedMemorySize, SM_TOT);
    k_all<<<GRIDM, 256, SM_TOT>>>((float*)d_out, feats, labels);
}